// round 5
// baseline (speedup 1.0000x reference)
#include <cuda_runtime.h>

// MaxPool2d k=2 s=2 valid, (32,64,224,224) fp32 -> (32,64,112,112).
// Pure HBM stream: 411 MB read + 103 MB write, zero reuse -> HBM roofline.
// R4: each thread computes a 4x4 output patch (4 output rows x 4 cols) from an
// 8-row x 8-col input patch. 16 LDG.128 issued as two front-batched groups of
// 8 (bounded register pressure; group 2 overlaps group 1's stores). 4 STG.128.
// Streaming hints (evict-first) since no byte is ever re-read.
// All accesses 16B-aligned: IW=224 floats, OW=112 floats, plane strides /16B.

#define NC_TOTAL   2048              // 32 * 64
#define IH         224
#define IW         224
#define OH         112
#define OW         112
#define IN_PLANE   (IH * IW)         // 50176
#define OUT_PLANE  (OH * OW)         // 12544
#define GROUPS_W   (OW / 4)          // 28 float4 groups per output row
#define ROWQUADS   (OH / 4)          // 28 quads of output rows
#define TOTAL_THREADS (NC_TOTAL * ROWQUADS * GROUPS_W)   // 1,605,632

__device__ __forceinline__ float4 ldcs4(const float4* p) { return __ldcs(p); }

__device__ __forceinline__ float4 pool2(const float4 a0, const float4 a1,
                                        const float4 b0, const float4 b1) {
    float4 o;
    o.x = fmaxf(fmaxf(a0.x, a0.y), fmaxf(b0.x, b0.y));
    o.y = fmaxf(fmaxf(a0.z, a0.w), fmaxf(b0.z, b0.w));
    o.z = fmaxf(fmaxf(a1.x, a1.y), fmaxf(b1.x, b1.y));
    o.w = fmaxf(fmaxf(a1.z, a1.w), fmaxf(b1.z, b1.w));
    return o;
}

__global__ __launch_bounds__(256)
void maxpool2d_k2s2_x4_kernel(const float* __restrict__ in, float* __restrict__ out) {
    int idx = blockIdx.x * blockDim.x + threadIdx.x;
    if (idx >= TOTAL_THREADS) return;

    int w8  = idx % GROUPS_W;            // output col group (4 cols -> 8 input cols)
    int t   = idx / GROUPS_W;
    int ohq = t % ROWQUADS;              // which quad of output rows
    int nc  = t / ROWQUADS;

    const int rstep = IW / 4;            // 56 float4 per input row
    const float4* r0 = reinterpret_cast<const float4*>(
        in + (size_t)nc * IN_PLANE + (size_t)(ohq * 8) * IW) + w8 * 2;

    float4* orow = reinterpret_cast<float4*>(
        out + (size_t)nc * OUT_PLANE + (size_t)(ohq * 4) * OW) + w8;
    const int ostep = OW / 4;            // 28 float4 per output row

    // ---- batch 1: input rows 0..3 -> output rows 0..1 ----
    float4 a0 = ldcs4(r0 + 0 * rstep + 0);
    float4 a1 = ldcs4(r0 + 0 * rstep + 1);
    float4 b0 = ldcs4(r0 + 1 * rstep + 0);
    float4 b1 = ldcs4(r0 + 1 * rstep + 1);
    float4 c0 = ldcs4(r0 + 2 * rstep + 0);
    float4 c1 = ldcs4(r0 + 2 * rstep + 1);
    float4 d0 = ldcs4(r0 + 3 * rstep + 0);
    float4 d1 = ldcs4(r0 + 3 * rstep + 1);

    __stcs(orow + 0 * ostep, pool2(a0, a1, b0, b1));
    __stcs(orow + 1 * ostep, pool2(c0, c1, d0, d1));

    // ---- batch 2: input rows 4..7 -> output rows 2..3 ----
    float4 e0 = ldcs4(r0 + 4 * rstep + 0);
    float4 e1 = ldcs4(r0 + 4 * rstep + 1);
    float4 f0 = ldcs4(r0 + 5 * rstep + 0);
    float4 f1 = ldcs4(r0 + 5 * rstep + 1);
    float4 g0 = ldcs4(r0 + 6 * rstep + 0);
    float4 g1 = ldcs4(r0 + 6 * rstep + 1);
    float4 h0 = ldcs4(r0 + 7 * rstep + 0);
    float4 h1 = ldcs4(r0 + 7 * rstep + 1);

    __stcs(orow + 2 * ostep, pool2(e0, e1, f0, f1));
    __stcs(orow + 3 * ostep, pool2(g0, g1, h0, h1));
}

extern "C" void kernel_launch(void* const* d_in, const int* in_sizes, int n_in,
                              void* d_out, int out_size) {
    const float* in = (const float*)d_in[0];
    float* out = (float*)d_out;
    int blocks = (TOTAL_THREADS + 255) / 256;   // 6272
    maxpool2d_k2s2_x4_kernel<<<blocks, 256>>>(in, out);
}

// round 6
// speedup vs baseline: 1.0042x; 1.0042x over previous
#include <cuda_runtime.h>

// MaxPool2d k=2 s=2 valid, (32,64,224,224) fp32 -> (32,64,112,112).
// Pure HBM stream (411 MB in + 103 MB out, zero reuse) -> HBM roofline kernel.
// R5: Blackwell 256-bit memory ops. One thread = 8 output cols of one output
// row: 4 front-batched LDG.256 (two per input row, fully independent -> MLP=4
// at 64B granularity = 128 B in flight/thread) + 1 STG.256.
// All offsets 32B-aligned (input group stride 64 B, output group stride 32 B).

#define NC_TOTAL   2048              // 32 * 64
#define IH         224
#define IW         224
#define OH         112
#define OW         112
#define IN_PLANE   (IH * IW)         // 50176
#define OUT_PLANE  (OH * OW)         // 12544
#define GROUPS_W   (OW / 8)          // 14 groups of 8 output cols per row
#define TOTAL_THREADS (NC_TOTAL * OH * GROUPS_W)   // 3,211,264

__device__ __forceinline__ void ldg256(const float* p, float v[8]) {
    asm volatile(
        "ld.global.nc.v8.f32 {%0,%1,%2,%3,%4,%5,%6,%7}, [%8];"
        : "=f"(v[0]), "=f"(v[1]), "=f"(v[2]), "=f"(v[3]),
          "=f"(v[4]), "=f"(v[5]), "=f"(v[6]), "=f"(v[7])
        : "l"(p));
}

__device__ __forceinline__ void stg256(float* p, const float v[8]) {
    asm volatile(
        "st.global.v8.f32 [%0], {%1,%2,%3,%4,%5,%6,%7,%8};"
        :: "l"(p),
           "f"(v[0]), "f"(v[1]), "f"(v[2]), "f"(v[3]),
           "f"(v[4]), "f"(v[5]), "f"(v[6]), "f"(v[7])
        : "memory");
}

__global__ __launch_bounds__(256)
void maxpool2d_k2s2_v8_kernel(const float* __restrict__ in, float* __restrict__ out) {
    int idx = blockIdx.x * blockDim.x + threadIdx.x;
    if (idx >= TOTAL_THREADS) return;

    int w16 = idx % GROUPS_W;            // group of 8 output cols -> 16 input cols
    int t   = idx / GROUPS_W;
    int oh  = t % OH;
    int nc  = t / OH;

    const float* r0 = in + (size_t)nc * IN_PLANE + (size_t)(oh * 2) * IW + w16 * 16;
    const float* r1 = r0 + IW;

    // Front-batch 4 independent 256-bit loads (no mid-thread consumption point).
    float a0[8], a1[8], b0[8], b1[8];
    ldg256(r0,     a0);   // row0 cols 0..7
    ldg256(r0 + 8, a1);   // row0 cols 8..15
    ldg256(r1,     b0);   // row1 cols 0..7
    ldg256(r1 + 8, b1);   // row1 cols 8..15

    float o[8];
#pragma unroll
    for (int j = 0; j < 4; j++) {
        o[j]     = fmaxf(fmaxf(a0[2*j], a0[2*j+1]), fmaxf(b0[2*j], b0[2*j+1]));
        o[j + 4] = fmaxf(fmaxf(a1[2*j], a1[2*j+1]), fmaxf(b1[2*j], b1[2*j+1]));
    }

    stg256(out + (size_t)nc * OUT_PLANE + (size_t)oh * OW + w16 * 8, o);
}

extern "C" void kernel_launch(void* const* d_in, const int* in_sizes, int n_in,
                              void* d_out, int out_size) {
    const float* in = (const float*)d_in[0];
    float* out = (float*)d_out;
    int blocks = (TOTAL_THREADS + 255) / 256;   // 12544
    maxpool2d_k2s2_v8_kernel<<<blocks, 256>>>(in, out);
}